// round 10
// baseline (speedup 1.0000x reference)
#include <cuda_runtime.h>
#include <math.h>

#define K 32
#define G 256
#define XMIN -6.5f
#define RANGE 13.0f
#define INV_H (G / RANGE)
#define H_STEP (RANGE / G)
#define INV_SQRT_2PI 0.3989422804014327f
#define S_CONST 0.8493218002880191f  // sqrt(0.5*log2(e))
#define EPS 2.2204460492503131e-16f
#define NB 148
#define WPB 24
#define THREADS 768

__device__ float2 g_tabF[G * K];  // (value, delta) per (g, comp)
__device__ float2 g_tabI[G * K];
__device__ int g_cnt;             // monotonic barrier ticket counter (replay-safe)

__device__ __forceinline__ float ex2f(float x) {
    float r;
    asm("ex2.approx.ftz.f32 %0, %1;" : "=f"(r) : "f"(x));
    return r;
}

__global__ void __launch_bounds__(THREADS, 1)
tt_fused(const float* __restrict__ X,
         const float* __restrict__ Wk0,
         const float* __restrict__ W10,
         const float* __restrict__ W21,
         const float* __restrict__ mu,
         const float* __restrict__ sigma,
         float* __restrict__ out, int n, int ntasks) {
    extern __shared__ float4 dyn[];
    float4* sF = dyn;            // [G*16] row g: 16 float4 = comps (2p,2p+1) as (v,d)
    float4* sI = dyn + G * 16;

    __shared__ float4 s_tab[K * K];      // folded coeffs
    __shared__ float w0s[K];
    __shared__ float4 sp[WPB][32];
    __shared__ float prodm[WPB][32][17];

    int tid = threadIdx.x;
    int lane = tid & 31;
    int w = tid >> 5;

    // ---- early X load (hides DRAM latency under phase A) ----
    int task = blockIdx.x + NB * w;
    int sidx = task * 32 + lane;
    float2 x = make_float2(0.f, 0.f);
    if (task < ntasks && sidx < n) x = ((const float2*)X)[sidx];

    // ---- phase A1: softmax folding (warps 0..15) ----
    if (w == 0) {
        float v = Wk0[lane];
        float mx = v;
#pragma unroll
        for (int o = 16; o; o >>= 1) mx = fmaxf(mx, __shfl_xor_sync(~0u, mx, o));
        float e = __expf(v - mx);
        float s = e;
#pragma unroll
        for (int o = 16; o; o >>= 1) s += __shfl_xor_sync(~0u, s, o);
        w0s[lane] = e / s;
    }

    float w10v[2], w21v[2], sgv[2], muv[2];
    if (w < 16) {
#pragma unroll
        for (int c = 0; c < 2; c++) {
            int j = w + c * 16;
            int idx = lane * K + j;
            float v10 = W10[idx];
            float v21 = W21[idx];
            sgv[c] = sigma[idx];
            muv[c] = mu[idx];
            float mx10 = v10, mx21 = v21;
#pragma unroll
            for (int o = 16; o; o >>= 1) {
                mx10 = fmaxf(mx10, __shfl_xor_sync(~0u, mx10, o));
                mx21 = fmaxf(mx21, __shfl_xor_sync(~0u, mx21, o));
            }
            float e10 = __expf(v10 - mx10);
            float e21 = __expf(v21 - mx21);
            float s10 = e10, s21 = e21;
#pragma unroll
            for (int o = 16; o; o >>= 1) {
                s10 += __shfl_xor_sync(~0u, s10, o);
                s21 += __shfl_xor_sync(~0u, s21, o);
            }
            w10v[c] = e10 / s10;
            w21v[c] = e21 / s21;
        }
    }
    __syncthreads();  // w0s ready

    if (w < 16) {
#pragma unroll
        for (int c = 0; c < 2; c++) {
            int j = w + c * 16;
            float inv_sg = 1.f / sgv[c];
            float4 t;
            t.x = S_CONST * inv_sg;
            t.y = -S_CONST * muv[c] * inv_sg;
            t.z = w21v[c] * INV_SQRT_2PI * inv_sg;
            t.w = w10v[c] * w0s[j] * INV_SQRT_2PI * inv_sg;
            s_tab[lane * K + j] = t;
        }
    }
    __syncthreads();  // s_tab ready

    // ---- phase A2: distributed table build (warps 0..3, 4 rows/block) ----
    if (w < 4) {
        int row = blockIdx.x + NB * w;      // 0..591 -> 512 valid rows
        if (row < 2 * G) {
            int tsel = row >> 8;            // 0 = F, 1 = I
            int g = row & (G - 1);
            float xa = XMIN + g * H_STEP;
            float xb = xa + H_STEP;
            int f = lane;
            float v0 = 0.f, v1 = 0.f;
            if (tsel == 0) {
#pragma unroll
                for (int j = 0; j < K; j++) {
                    float4 t = s_tab[f * K + j];
                    float ua = fmaf(xa, t.x, t.y);
                    float ub = fmaf(xb, t.x, t.y);
                    v0 = fmaf(t.w, ex2f(-ua * ua), v0);
                    v1 = fmaf(t.w, ex2f(-ub * ub), v1);
                }
                float2 e; e.x = v0; e.y = (g < G - 1) ? (v1 - v0) : 0.f;
                g_tabF[g * K + f] = e;
            } else {
#pragma unroll
                for (int i = 0; i < K; i++) {
                    float4 t = s_tab[i * K + f];
                    float ua = fmaf(xa, t.x, t.y);
                    float ub = fmaf(xb, t.x, t.y);
                    v0 = fmaf(t.z, ex2f(-ua * ua), v0);
                    v1 = fmaf(t.z, ex2f(-ub * ub), v1);
                }
                float2 e; e.x = v0; e.y = (g < G - 1) ? (v1 - v0) : 0.f;
                g_tabI[g * K + f] = e;
            }
        }
    }

    // ---- device-wide barrier (monotonic ticket; all 148 blocks co-resident) ----
    __threadfence();
    __syncthreads();
    if (tid == 0) {
        int ticket = atomicAdd(&g_cnt, 1) + 1;
        int target = ((ticket + NB - 1) / NB) * NB;  // this replay's cohort end
        while (atomicAdd(&g_cnt, 0) < target) { }
        __threadfence();
    }
    __syncthreads();

    // ---- phase B: stage tables to smem ----
    const float4* gF = (const float4*)g_tabF;
    const float4* gI = (const float4*)g_tabI;
    for (int i = tid; i < G * 16; i += THREADS) sF[i] = gF[i];
    for (int i = tid; i < G * 16; i += THREADS) sI[i] = gI[i];
    __syncthreads();

    // ---- phase C: warp-cooperative interpolation + dot ----
    if (task < ntasks) {
        float t0 = (x.x - XMIN) * INV_H;
        float t1 = (x.y - XMIN) * INV_H;
        float g0f = fminf(fmaxf(floorf(t0), 0.f), (float)(G - 2));
        float g1f = fminf(fmaxf(floorf(t1), 0.f), (float)(G - 2));
        sp[w][lane] = make_float4(g0f, t0 - g0f, g1f, t1 - g1f);
        __syncwarp();

        int half = lane >> 4;   // lanes 0-15: even sample of pair; 16-31: odd
        int pair = lane & 15;   // component pair (comps 2p, 2p+1)

#pragma unroll
        for (int t = 0; t < 16; t++) {
            float4 p = sp[w][2 * t + half];
            float4 fF = sF[((int)p.x) * 16 + pair];
            float4 fI = sI[((int)p.z) * 16 + pair];
            float vF0 = fmaf(p.y, fF.y, fF.x);
            float vF1 = fmaf(p.y, fF.w, fF.z);
            float vI0 = fmaf(p.w, fI.y, fI.x);
            float vI1 = fmaf(p.w, fI.w, fI.z);
            prodm[w][2 * t + half][pair] = vF0 * vI0 + vF1 * vI1;
        }
        __syncwarp();

        float acc = 0.f;
#pragma unroll
        for (int i = 0; i < 16; i++) acc += prodm[w][lane][i];

        if (sidx < n) out[sidx] = __logf(acc + EPS);
    }
}

extern "C" void kernel_launch(void* const* d_in, const int* in_sizes, int n_in,
                              void* d_out, int out_size) {
    const float* X     = (const float*)d_in[0];
    const float* Wk0   = (const float*)d_in[1];
    const float* Wk1k0 = (const float*)d_in[2];
    const float* Wk2k1 = (const float*)d_in[3];
    const float* mu    = (const float*)d_in[4];
    const float* sigma = (const float*)d_in[5];
    float* out = (float*)d_out;
    int n = in_sizes[0] / 2;

    int dyn_bytes = 2 * G * K * (int)sizeof(float2);  // 131072
    cudaFuncSetAttribute(tt_fused, cudaFuncAttributeMaxDynamicSharedMemorySize, dyn_bytes);

    int ntasks = (n + 31) / 32;
    tt_fused<<<NB, THREADS, dyn_bytes>>>(X, Wk0, Wk1k0, Wk2k1, mu, sigma, out, n, ntasks);
}

// round 11
// speedup vs baseline: 1.2608x; 1.2608x over previous
#include <cuda_runtime.h>
#include <math.h>

#define K 32
#define G 256
#define XMIN -6.5f
#define RANGE 13.0f
#define INV_H (G / RANGE)
#define H_STEP (RANGE / G)
#define INV_SQRT_2PI 0.3989422804014327f
#define S_CONST 0.8493218002880191f  // sqrt(0.5*log2(e))
#define EPS 2.2204460492503131e-16f
#define NCHUNK 9                     // ceil((G-1)/31)
#define WPB 8

__device__ float2 g_tabF[G * K];  // (value, delta) per (g, comp)
__device__ float2 g_tabI[G * K];

__device__ __forceinline__ float ex2f(float x) {
    float r;
    asm("ex2.approx.ftz.f32 %0, %1;" : "=f"(r) : "f"(x));
    return r;
}

// ---------------- fused prep + build (float2: value + delta) ----------------
// grid dim3(NCHUNK, 2), 512 threads. Warp w owns functions {w, w+16}; lane is a
// grid point within a 31-wide overlapping chunk (slope via shfl from lane+1).
__global__ void __launch_bounds__(512) build_kernel(const float* __restrict__ Wk0,
                                                    const float* __restrict__ W10,
                                                    const float* __restrict__ W21,
                                                    const float* __restrict__ mu,
                                                    const float* __restrict__ sigma) {
    __shared__ float4 s_tab[K * K];
    __shared__ float w0s[K];

    int lane = threadIdx.x & 31;
    int w = threadIdx.x >> 5;

    if (w == 0) {
        float v = Wk0[lane];
        float mx = v;
#pragma unroll
        for (int o = 16; o; o >>= 1) mx = fmaxf(mx, __shfl_xor_sync(~0u, mx, o));
        float e = __expf(v - mx);
        float s = e;
#pragma unroll
        for (int o = 16; o; o >>= 1) s += __shfl_xor_sync(~0u, s, o);
        w0s[lane] = e / s;
    }

    float w10v[2], w21v[2], sgv[2], muv[2];
#pragma unroll
    for (int c = 0; c < 2; c++) {
        int j = w + c * 16;
        int idx = lane * K + j;
        float v10 = W10[idx];
        float v21 = W21[idx];
        sgv[c] = sigma[idx];
        muv[c] = mu[idx];
        float mx10 = v10, mx21 = v21;
#pragma unroll
        for (int o = 16; o; o >>= 1) {
            mx10 = fmaxf(mx10, __shfl_xor_sync(~0u, mx10, o));
            mx21 = fmaxf(mx21, __shfl_xor_sync(~0u, mx21, o));
        }
        float e10 = __expf(v10 - mx10);
        float e21 = __expf(v21 - mx21);
        float s10 = e10, s21 = e21;
#pragma unroll
        for (int o = 16; o; o >>= 1) {
            s10 += __shfl_xor_sync(~0u, s10, o);
            s21 += __shfl_xor_sync(~0u, s21, o);
        }
        w10v[c] = e10 / s10;
        w21v[c] = e21 / s21;
    }
    __syncthreads();

#pragma unroll
    for (int c = 0; c < 2; c++) {
        int j = w + c * 16;
        float inv_sg = 1.f / sgv[c];
        float4 t;
        t.x = S_CONST * inv_sg;
        t.y = -S_CONST * muv[c] * inv_sg;
        t.z = w21v[c] * INV_SQRT_2PI * inv_sg;
        t.w = w10v[c] * w0s[j] * INV_SQRT_2PI * inv_sg;
        s_tab[lane * K + j] = t;
    }
    __syncthreads();

    int chunk = blockIdx.x;
    int tsel = blockIdx.y;
    int g = chunk * 31 + lane;
    if (g > G - 1) g = G - 1;
    float x = XMIN + g * H_STEP;

#pragma unroll
    for (int c = 0; c < 2; c++) {
        int f = w + c * 16;
        float v = 0.f;
        if (tsel == 0) {
#pragma unroll
            for (int j = 0; j < K; j++) {
                float4 t = s_tab[f * K + j];
                float u = fmaf(x, t.x, t.y);
                v = fmaf(t.w, ex2f(-u * u), v);
            }
        } else {
#pragma unroll
            for (int i = 0; i < K; i++) {
                float4 t = s_tab[i * K + f];
                float u = fmaf(x, t.x, t.y);
                v = fmaf(t.z, ex2f(-u * u), v);
            }
        }
        float vn = __shfl_down_sync(0xffffffffu, v, 1);
        if (lane < 31 && g < G - 1) {
            float2 e;
            e.x = v;
            e.y = vn - v;
            if (tsel == 0) g_tabF[g * K + f] = e;
            else           g_tabI[g * K + f] = e;
        }
    }
}

// ---------------- main: tables L1-resident via LDG, no staging ----------------
__global__ void __launch_bounds__(256) tt_main(const float* __restrict__ X,
                                               float* __restrict__ out,
                                               int n, int ntasks) {
    __shared__ float4 sp[WPB][32];
    __shared__ float prodm[WPB][32][17];

    int tid = threadIdx.x;
    int lane = tid & 31;
    int w = tid >> 5;

    int task = blockIdx.x * WPB + w;
    if (task >= ntasks) return;

    int sidx = task * 32 + lane;
    float2 x = make_float2(0.f, 0.f);
    if (sidx < n) x = ((const float2*)X)[sidx];

    float t0 = (x.x - XMIN) * INV_H;
    float t1 = (x.y - XMIN) * INV_H;
    float g0f = fminf(fmaxf(floorf(t0), 0.f), (float)(G - 2));
    float g1f = fminf(fmaxf(floorf(t1), 0.f), (float)(G - 2));
    sp[w][lane] = make_float4(g0f, t0 - g0f, g1f, t1 - g1f);
    __syncwarp();

    const float4* tF = (const float4*)g_tabF;  // row g: 16 float4 (comps 2p,2p+1 as v,d)
    const float4* tI = (const float4*)g_tabI;

    int half = lane >> 4;   // lanes 0-15: even sample of pair; 16-31: odd
    int pair = lane & 15;   // component pair (comps 2p, 2p+1)

#pragma unroll
    for (int t = 0; t < 16; t++) {
        float4 p = sp[w][2 * t + half];
        float4 fF = __ldg(&tF[((int)p.x) * 16 + pair]);
        float4 fI = __ldg(&tI[((int)p.z) * 16 + pair]);
        float vF0 = fmaf(p.y, fF.y, fF.x);
        float vF1 = fmaf(p.y, fF.w, fF.z);
        float vI0 = fmaf(p.w, fI.y, fI.x);
        float vI1 = fmaf(p.w, fI.w, fI.z);
        prodm[w][2 * t + half][pair] = vF0 * vI0 + vF1 * vI1;
    }
    __syncwarp();

    float acc = 0.f;
#pragma unroll
    for (int i = 0; i < 16; i++) acc += prodm[w][lane][i];

    if (sidx < n) out[sidx] = __logf(acc + EPS);
}

extern "C" void kernel_launch(void* const* d_in, const int* in_sizes, int n_in,
                              void* d_out, int out_size) {
    const float* X     = (const float*)d_in[0];
    const float* Wk0   = (const float*)d_in[1];
    const float* Wk1k0 = (const float*)d_in[2];
    const float* Wk2k1 = (const float*)d_in[3];
    const float* mu    = (const float*)d_in[4];
    const float* sigma = (const float*)d_in[5];
    float* out = (float*)d_out;
    int n = in_sizes[0] / 2;

    build_kernel<<<dim3(NCHUNK, 2), 512>>>(Wk0, Wk1k0, Wk2k1, mu, sigma);
    int ntasks = (n + 31) / 32;
    int blocks = (ntasks + WPB - 1) / WPB;
    tt_main<<<blocks, 256>>>(X, out, n, ntasks);
}